// round 7
// baseline (speedup 1.0000x reference)
#include <cuda_runtime.h>

// CNF_plain: B=131072 samples, D=8, H=128.
// dz_dt  = MLP(concat(z,t))          -> out[0 .. B*8)
// dlogp  = -trace(d(dz_dt)/dz)       -> out[B*8 .. B*9)
//
// Trace trick: trace = sum_j s2_j * sum_k s1_k * G[k,j]
//   with G[k,j] = W2[k,j] * sum_d W3[j,d] * W1[d,k]  (sample-independent,
//   precomputed once), s1 = 1-h1^2, s2 = 1-h2^2.
// Inner fused matvec pair uses packed fma.rn.f32x2 (FFMA2). SPW=8 samples/warp
// amortizes the 1024B/warp-k of W2+G shared loads over 32 FFMA2.
// h1/s1 in one 20-float row (80B lane stride, odd 16B count -> conflict-free).
// W3 transposed into padded rows so layer 3 is float4-fed.
// z loads for the NEXT group are prefetched into registers so LDG latency
// overlaps the current group's compute.

#define BTOT 131072
#define DD 8
#define HH 128
#define SPW 8                   // samples per warp per group
#define WARPS 8
#define NTHREADS (WARPS * 32)
#define NGROUPS (BTOT / SPW)
#define HSROW 20                // h[8] | s[8] | pad[4]  (80B, stride16=5: odd)
#define H2STRIDE 132            // padded stride (33 x 16B, odd) h2 + W3T rows
#define WBUF (HH * HSROW + 64)  // hs rows + z staging = 2624 floats

typedef unsigned long long u64;

// d = (a.lo*b.lo+c.lo, a.hi*b.hi+c.hi)  — packed f32x2 FMA (sm_100+)
#define FMA2(d, a, b, c) \
    asm("fma.rn.f32x2 %0, %1, %2, %3;" : "=l"(d) : "l"(a), "l"(b), "l"(c))
#define PACK2(d, x, y) \
    asm("mov.b64 %0, {%1, %2};" : "=l"(d) : "f"(x), "f"(y))
#define UNPACK2(x, y, d) \
    asm("mov.b64 {%0, %1}, %2;" : "=f"(x), "=f"(y) : "l"(d))
// 16B shared load as two packed b64 (two f32 pairs)
#define LDSV2B64(d0, d1, saddr) \
    asm("ld.shared.v2.b64 {%0, %1}, [%2];" : "=l"(d0), "=l"(d1) : "r"(saddr))

__device__ float g_G[HH * HH];

__global__ void precompute_G_kernel(const float* __restrict__ W1,
                                    const float* __restrict__ W2,
                                    const float* __restrict__ W3) {
    int j = threadIdx.x;   // 0..127
    int k = blockIdx.x;    // 0..127
    float m = 0.0f;
#pragma unroll
    for (int d = 0; d < DD; ++d)
        m = fmaf(W3[j * DD + d], W1[d * HH + k], m);
    g_G[k * HH + j] = W2[k * HH + j] * m;
}

__global__ __launch_bounds__(NTHREADS, 1)
void cnf_kernel(const float* __restrict__ z,
                const float* __restrict__ tptr,
                const float* __restrict__ W1,
                const float* __restrict__ b1,
                const float* __restrict__ W2,
                const float* __restrict__ b2,
                const float* __restrict__ W3,
                const float* __restrict__ b3,
                float* __restrict__ out) {
    extern __shared__ float smem[];
    float* sW2   = smem;                       // 16384 floats
    float* sG    = sW2 + HH * HH;              // 16384
    float* sW1   = sG + HH * HH;               // 1152
    float* sb1   = sW1 + (DD + 1) * HH;        // 128
    float* sb2   = sb1 + HH;                   // 128
    float* sW3T  = sb2 + HH;                   // 8 x 132 = 1056 (transposed, padded)
    float* sb3   = sW3T + DD * H2STRIDE;       // 8
    float* wbase = sb3 + 8;                    // WARPS * WBUF (16B-aligned)

    for (int i = threadIdx.x; i < HH * HH; i += NTHREADS) {
        sW2[i] = W2[i];
        sG[i]  = g_G[i];
    }
    for (int i = threadIdx.x; i < (DD + 1) * HH; i += NTHREADS) sW1[i] = W1[i];
    if (threadIdx.x < HH) {
        sb1[threadIdx.x] = b1[threadIdx.x];
        sb2[threadIdx.x] = b2[threadIdx.x];
    }
    for (int i = threadIdx.x; i < HH * DD; i += NTHREADS) {
        int j = i >> 3, d = i & 7;
        sW3T[d * H2STRIDE + j] = W3[i];        // transpose: coalesced read
    }
    if (threadIdx.x < DD) sb3[threadIdx.x] = b3[threadIdx.x];
    __syncthreads();

    const float t = tptr[0];
    const int warp = threadIdx.x >> 5;
    const int lane = threadIdx.x & 31;
    float* hsw = wbase + warp * WBUF;  // [k][HSROW]: h 0..7, s 8..15; h2 reuse
    float* zw  = hsw + HH * HSROW;     // z staging: [s][d], 64 floats

    // Shared-window 32-bit base addresses for raw ld.shared asm
    const unsigned w_base =
        (unsigned)__cvta_generic_to_shared(sW2) + (unsigned)(16 * lane);
    const unsigned g_base =
        (unsigned)__cvta_generic_to_shared(sG) + (unsigned)(16 * lane);

    float* logp_out = out + (size_t)BTOT * DD;

    const int gstride = gridDim.x * WARPS;
    int g = blockIdx.x * WARPS + warp;

    // Prefetch first group's z (64 consecutive floats per warp, coalesced)
    float zr0 = 0.0f, zr1 = 0.0f;
    if (g < NGROUPS) {
        zr0 = z[(size_t)g * 64 + lane];
        zr1 = z[(size_t)g * 64 + lane + 32];
    }

    for (; g < NGROUPS; g += gstride) {
        const int s0 = g * SPW;

        // Stage this group's z, then immediately prefetch the next group's
        // so the LDG latency overlaps the whole group's compute.
        zw[lane]      = zr0;
        zw[lane + 32] = zr1;
        __syncwarp();
        {
            const int gn = g + gstride;
            if (gn < NGROUPS) {
                zr0 = z[(size_t)gn * 64 + lane];
                zr1 = z[(size_t)gn * 64 + lane + 32];
            }
        }

        // ---- Layer 1: lane handles k = lane + 32*i; W1 column in registers ----
#pragma unroll
        for (int i = 0; i < 4; ++i) {
            const int k = lane + 32 * i;
            float w1r[DD];
#pragma unroll
            for (int d = 0; d < DD; ++d) w1r[d] = sW1[d * HH + k];
            const float base0 = fmaf(t, sW1[8 * HH + k], sb1[k]);
            float hv[SPW], sv[SPW];
#pragma unroll
            for (int s = 0; s < SPW; ++s) {
                const float4 za = *(const float4*)&zw[s * DD];
                const float4 zb = *(const float4*)&zw[s * DD + 4];
                float a = base0;
                a = fmaf(za.x, w1r[0], a); a = fmaf(za.y, w1r[1], a);
                a = fmaf(za.z, w1r[2], a); a = fmaf(za.w, w1r[3], a);
                a = fmaf(zb.x, w1r[4], a); a = fmaf(zb.y, w1r[5], a);
                a = fmaf(zb.z, w1r[6], a); a = fmaf(zb.w, w1r[7], a);
                float h = tanhf(a);
                hv[s] = h;
                sv[s] = 1.0f - h * h;
            }
            float* row = hsw + k * HSROW;   // 80B lane stride: conflict-free
            *(float4*)&row[0]  = make_float4(hv[0], hv[1], hv[2], hv[3]);
            *(float4*)&row[4]  = make_float4(hv[4], hv[5], hv[6], hv[7]);
            *(float4*)&row[8]  = make_float4(sv[0], sv[1], sv[2], sv[3]);
            *(float4*)&row[12] = make_float4(sv[4], sv[5], sv[6], sv[7]);
        }
        __syncwarp();

        // ---- Layer 2 matvec (a2 = h1@W2+b2) fused with trace matvec (v = s1@G)
        // Packed f32x2: lane owns j = 4*lane..4*lane+3 as 2 packed pairs,
        // for 8 samples. W2/G pairs arrive pre-packed from ld.shared.v2.b64.
        u64 acc2[SPW][2], vac2[SPW][2];
        {
            u64 b2p0, b2p1;
            const unsigned b2a =
                (unsigned)__cvta_generic_to_shared(sb2) + (unsigned)(16 * lane);
            LDSV2B64(b2p0, b2p1, b2a);
#pragma unroll
            for (int s = 0; s < SPW; ++s) {
                acc2[s][0] = b2p0; acc2[s][1] = b2p1;
                vac2[s][0] = 0ull; vac2[s][1] = 0ull;
            }
        }
#pragma unroll 2
        for (int k = 0; k < HH; ++k) {
            const float* row = hsw + k * HSROW;
            const float4 ha = *(const float4*)&row[0];   // broadcast reads
            const float4 hb = *(const float4*)&row[4];
            const float4 sa = *(const float4*)&row[8];
            const float4 sb = *(const float4*)&row[12];
            u64 wp0, wp1, gp0, gp1;
            LDSV2B64(wp0, wp1, w_base + (unsigned)(k * (HH * 4)));
            LDSV2B64(gp0, gp1, g_base + (unsigned)(k * (HH * 4)));
            const float hv[SPW] = {ha.x, ha.y, ha.z, ha.w, hb.x, hb.y, hb.z, hb.w};
            const float sv[SPW] = {sa.x, sa.y, sa.z, sa.w, sb.x, sb.y, sb.z, sb.w};
#pragma unroll
            for (int s = 0; s < SPW; ++s) {
                u64 hd, sd;
                PACK2(hd, hv[s], hv[s]);
                PACK2(sd, sv[s], sv[s]);
                FMA2(acc2[s][0], hd, wp0, acc2[s][0]);
                FMA2(acc2[s][1], hd, wp1, acc2[s][1]);
                FMA2(vac2[s][0], sd, gp0, vac2[s][0]);
                FMA2(vac2[s][1], sd, gp1, vac2[s][1]);
            }
        }
        __syncwarp();  // all lanes done reading hs rows before reuse as h2 buffer

        // ---- tanh + trace partials; store h2 [s][j] with padded stride ----
        float tpart[SPW];
#pragma unroll
        for (int s = 0; s < SPW; ++s) {
            float a[4], v[4], h2v[4];
            UNPACK2(a[0], a[1], acc2[s][0]); UNPACK2(a[2], a[3], acc2[s][1]);
            UNPACK2(v[0], v[1], vac2[s][0]); UNPACK2(v[2], v[3], vac2[s][1]);
            float tp = 0.0f;
#pragma unroll
            for (int jj = 0; jj < 4; ++jj) {
                float h = tanhf(a[jj]);
                h2v[jj] = h;
                tp = fmaf(v[jj], 1.0f - h * h, tp);
            }
            tpart[s] = tp;
            *(float4*)&hsw[s * H2STRIDE + 4 * lane] =
                make_float4(h2v[0], h2v[1], h2v[2], h2v[3]);
        }
        __syncwarp();

        // ---- Trace: butterfly-reduce partials across warp ----
#pragma unroll
        for (int off = 16; off; off >>= 1) {
#pragma unroll
            for (int s = 0; s < SPW; ++s)
                tpart[s] += __shfl_xor_sync(0xffffffffu, tpart[s], off);
        }
        if (lane == 0) {
#pragma unroll
            for (int s = 0; s < SPW; ++s) logp_out[s0 + s] = -tpart[s];
        }

        // ---- dz/dt: 64 items = (8 samples x 8 dims); float4-fed dots ----
        {
            const int d = lane & 7;
            const float* w3row = sW3T + d * H2STRIDE;
#pragma unroll
            for (int i = 0; i < 2; ++i) {
                const int s = (lane >> 3) + 4 * i;
                const float* h2row = hsw + s * H2STRIDE;
                float o = sb3[d];
#pragma unroll 8
                for (int j = 0; j < HH; j += 4) {
                    const float4 h4 = *(const float4*)&h2row[j];
                    const float4 w4 = *(const float4*)&w3row[j];
                    o = fmaf(h4.x, w4.x, o); o = fmaf(h4.y, w4.y, o);
                    o = fmaf(h4.z, w4.z, o); o = fmaf(h4.w, w4.w, o);
                }
                out[(size_t)(s0 + s) * DD + d] = o;  // coalesced 128B per wave
            }
        }
        __syncwarp();  // h2 reads done before next iter's layer-1 hsw stores
    }
}

extern "C" void kernel_launch(void* const* d_in, const int* in_sizes, int n_in,
                              void* d_out, int out_size) {
    const float* z  = (const float*)d_in[0];
    // d_in[1] = logp_z (unused by the math)
    const float* t  = (const float*)d_in[2];
    const float* W1 = (const float*)d_in[3];
    const float* b1 = (const float*)d_in[4];
    const float* W2 = (const float*)d_in[5];
    const float* b2 = (const float*)d_in[6];
    const float* W3 = (const float*)d_in[7];
    const float* b3 = (const float*)d_in[8];
    float* out = (float*)d_out;

    precompute_G_kernel<<<HH, HH>>>(W1, W2, W3);

    const int smem_bytes =
        (2 * HH * HH + (DD + 1) * HH + HH + HH + DD * H2STRIDE + 8 +
         WARPS * WBUF) * (int)sizeof(float);  // 224,960 B = 219.7 KB < 227 KB
    cudaFuncSetAttribute(cnf_kernel,
                         cudaFuncAttributeMaxDynamicSharedMemorySize, smem_bytes);

    int nsm = 148;
    cudaDeviceGetAttribute(&nsm, cudaDevAttrMultiProcessorCount, 0);

    cnf_kernel<<<nsm, NTHREADS, smem_bytes>>>(z, t, W1, b1, W2, b2, W3, b3, out);
}